// round 8
// baseline (speedup 1.0000x reference)
#include <cuda_runtime.h>

#define NN 8192
#define NE 65536

typedef unsigned long long ull;

// ---------------- zeroed scratch blob (single memset) -----------------------
#define OFF_DEG    0
#define OFF_OUTCNT 8192
#define OFF_AGG1   16384
#define OFF_AGG2   409600
#define OFF_AGGM   671744
#define OFF_AGGL   802816
#define ZFLOATS    933888
__device__ __align__(16) float g_zbuf[ZFLOATS];

// ---------------- other scratch ---------------------------------------------
__device__ __align__(16) float g_T1[NN * 48 * 8];
__device__ __align__(16) float g_Tb1[NN * 48];
__device__ __align__(16) float g_T2[NN * 32 * 8];
__device__ __align__(16) float g_Tb2[NN * 32];
__device__ __align__(16) float g_h1[NN * 48];
__device__ __align__(16) float g_hm[NN * 16];
__device__ __align__(16) float g_hl[NN * 16];
__device__ __align__(16) float g_sea[NE * 8];   // edge_attr in src-sorted order
__device__ int   g_sdst[NE];                    // dst in src-sorted order
__device__ int   g_off[NN + 1];                 // CSR offsets by src
__device__ int   g_cursor[NN];
// pair-interleaved weights: Wtp[(k/2)*(2*NC) + c*2 + (k&1)] = W[k][c]
__device__ __align__(16) float g_Wtp1[64 * 432];
__device__ __align__(16) float g_Wtp2[48 * 288];
__device__ float g_dinv[NN];
__device__ float g_invdeg[NN];

// ---------------- packed fp32x2 helpers (Blackwell FFMA2) -------------------
__device__ __forceinline__ void fma2(ull& d, ull a, ull b) {
    asm("fma.rn.f32x2 %0, %1, %2, %0;" : "+l"(d) : "l"(a), "l"(b));
}
__device__ __forceinline__ float2 unpack2(ull v) {
    float lo, hi;
    asm("mov.b64 {%0, %1}, %2;" : "=f"(lo), "=f"(hi) : "l"(v));
    return make_float2(lo, hi);
}

__device__ __forceinline__ void red_add_v4(float* p, float a, float b, float c, float d) {
    asm volatile("red.global.add.v4.f32 [%0], {%1,%2,%3,%4};"
                 :: "l"(p), "f"(a), "f"(b), "f"(c), "f"(d) : "memory");
}

// ---------------- prep: degree/outdeg counts + pair-interleaved weights -----
__global__ void prep_kernel(const int* __restrict__ ei,
                            const float* __restrict__ nn1w, const float* __restrict__ nn1b,
                            const float* __restrict__ nn2w, const float* __restrict__ nn2b,
                            int* __restrict__ outcnt, int* __restrict__ deg,
                            float* __restrict__ Wtp1, float* __restrict__ Wtp2) {
    int bx = blockIdx.x, t = threadIdx.x;
    if (bx < 256) {
        int e = bx * 256 + t;
        atomicAdd(&outcnt[ei[e]], 1);
        atomicAdd(&deg[ei[NE + e]], 1);
    } else if (bx < 364) {               // 27648 elems: K=64, CO=48, NC=432
        int idx = (bx - 256) * 256 + t;
        int i2 = idx / 864, rem = idx - i2 * 864;
        int c = rem >> 1, i = i2 * 2 + (rem & 1);
        float v;
        if (c < 384) { int o = c >> 3, s = c & 7; v = nn1w[s * 3072 + i * 48 + o]; }
        else         { int o = c - 384;           v = nn1b[i * 48 + o]; }
        Wtp1[idx] = v;
    } else {                              // 13824 elems: K=48, CO=32, NC=288
        int idx = (bx - 364) * 256 + t;
        if (idx < 13824) {
            int i2 = idx / 576, rem = idx - i2 * 576;
            int c = rem >> 1, i = i2 * 2 + (rem & 1);
            float v;
            if (c < 256) { int o = c >> 3, s = c & 7; v = nn2w[s * 1536 + i * 32 + o]; }
            else         { int o = c - 256;           v = nn2b[i * 32 + o]; }
            Wtp2[idx] = v;
        }
    }
}

// ---------------- block 0: exclusive scan of outcnt; blocks 1..8: dinv ------
__global__ void scan_dinv_kernel(const int* __restrict__ outcnt, const int* __restrict__ deg,
                                 int* __restrict__ off, int* __restrict__ cursor,
                                 float* __restrict__ dinv, float* __restrict__ invdeg) {
    int t = threadIdx.x;
    if (blockIdx.x == 0) {
        __shared__ int wsum[32];
        int base = t * 8;
        int v[8];
        int s = 0;
#pragma unroll
        for (int j = 0; j < 8; j++) { v[j] = outcnt[base + j]; s += v[j]; }
        int lane = t & 31, wid = t >> 5;
        int inc = s;
#pragma unroll
        for (int d = 1; d < 32; d <<= 1) {
            int n = __shfl_up_sync(0xFFFFFFFFu, inc, d);
            if (lane >= d) inc += n;
        }
        int excl_warp = inc - s;
        if (lane == 31) wsum[wid] = inc;
        __syncthreads();
        if (t < 32) {
            int w = wsum[t];
            int wi = w;
#pragma unroll
            for (int d = 1; d < 32; d <<= 1) {
                int n = __shfl_up_sync(0xFFFFFFFFu, wi, d);
                if (t >= d) wi += n;
            }
            wsum[t] = wi - w;
        }
        __syncthreads();
        int run = wsum[wid] + excl_warp;
#pragma unroll
        for (int j = 0; j < 8; j++) {
            off[base + j] = run;
            cursor[base + j] = run;
            run += v[j];
        }
        if (t == 1023) off[NN] = NE;
    } else {
        int n = (blockIdx.x - 1) * 1024 + t;
        float d = (float)deg[n] + 1.0f;
        dinv[n] = rsqrtf(d);
        invdeg[n] = 1.0f / d;
    }
}

// ---------------- scatter edge payloads into src-sorted order ---------------
__global__ void perm_kernel(const int* __restrict__ ei, const float* __restrict__ ea,
                            int* __restrict__ cursor,
                            int* __restrict__ sdst, float* __restrict__ sea) {
    int e = blockIdx.x * 256 + threadIdx.x;
    int s = ei[e];
    int pos = atomicAdd(&cursor[s], 1);
    sdst[pos] = ei[NE + e];
    const float4* ev = reinterpret_cast<const float4*>(ea + e * 8);
    float4* sv = reinterpret_cast<float4*>(sea + pos * 8);
    sv[0] = ev[0];
    sv[1] = ev[1];
}

// ---------------- node GEMM: k-paired FFMA2, spill-free (<=64 regs) ---------
// Block: 256 thr, 32 nodes x 128 cols per tile, 2 tiles. Thread: 4 nodes x
// 4 cols (c = cbase + lane + 32j). One k-pair per inner iter:
//   4 broadcast LDS.64 (x) + 4 strided LDS.64 (w) + 16 FFMA2, unroll 1.
template<int K, int CO>
__global__ void __launch_bounds__(256, 4) node_gemm_kernel(
        const float* __restrict__ X, const float* __restrict__ Wtp,
        float* __restrict__ T, float* __restrict__ Tb) {
    constexpr int NC = CO * 9;
    constexpr int KH = K / 2;
    __shared__ __align__(16) float ws[KH * 256];   // ull[KH][128]
    __shared__ __align__(16) float xs[32 * K];     // node-major
    int tid = threadIdx.x;
    int cbase = blockIdx.x * 128;

    // fill ws as ull pairs: wsu[r*128 + j] = (W[2r][cbase+j], W[2r+1][cbase+j])
    {
        ulonglong2* wsu2 = reinterpret_cast<ulonglong2*>(ws);
        const ulonglong2* Wu2 = reinterpret_cast<const ulonglong2*>(Wtp);
        for (int idx = tid; idx < KH * 64; idx += 256) {
            int r = idx >> 6, j = idx & 63;
            int c = cbase + j * 2;
            wsu2[idx] = (c < NC) ? Wu2[(r * NC + c) >> 1]
                                 : make_ulonglong2(0ull, 0ull);
        }
    }

    int lane = tid & 31, wd = tid >> 5;
    const ull* wsu = reinterpret_cast<const ull*>(ws);
    const float4* X4 = reinterpret_cast<const float4*>(X);
    float4* xs4 = reinterpret_cast<float4*>(xs);

    for (int tile = 0; tile < 2; tile++) {
        int n0 = (blockIdx.y * 2 + tile) * 32;
        __syncthreads();
        for (int idx = tid; idx < 32 * K / 4; idx += 256)
            xs4[idx] = X4[n0 * (K / 4) + idx];
        __syncthreads();

        ull acc[4][4];
#pragma unroll
        for (int n = 0; n < 4; n++)
#pragma unroll
            for (int j = 0; j < 4; j++) acc[n][j] = 0ull;

        const ull* xrow = reinterpret_cast<const ull*>(xs + (wd * 4) * K);
        const ull* wcol = wsu + lane;
#pragma unroll 1
        for (int r = 0; r < KH; r++) {
            ull x0 = xrow[0 * KH + r];
            ull x1 = xrow[1 * KH + r];
            ull x2 = xrow[2 * KH + r];
            ull x3 = xrow[3 * KH + r];
            const ull* wr = wcol + r * 128;
            ull w0 = wr[0], w1 = wr[32], w2 = wr[64], w3 = wr[96];
            fma2(acc[0][0], x0, w0); fma2(acc[0][1], x0, w1);
            fma2(acc[0][2], x0, w2); fma2(acc[0][3], x0, w3);
            fma2(acc[1][0], x1, w0); fma2(acc[1][1], x1, w1);
            fma2(acc[1][2], x1, w2); fma2(acc[1][3], x1, w3);
            fma2(acc[2][0], x2, w0); fma2(acc[2][1], x2, w1);
            fma2(acc[2][2], x2, w2); fma2(acc[2][3], x2, w3);
            fma2(acc[3][0], x3, w0); fma2(acc[3][1], x3, w1);
            fma2(acc[3][2], x3, w2); fma2(acc[3][3], x3, w3);
        }

#pragma unroll
        for (int n = 0; n < 4; n++) {
            int na = n0 + wd * 4 + n;
#pragma unroll
            for (int j = 0; j < 4; j++) {
                int c = cbase + lane + 32 * j;
                if (c < NC) {
                    float2 p = unpack2(acc[n][j]);
                    float v = p.x + p.y;
                    if (c < CO * 8) T[na * (CO * 8) + c] = v;
                    else            Tb[na * CO + (c - CO * 8)] = v;
                }
            }
        }
    }
}

// ---------------- edge NNConv: node-parallel over src-CSR -------------------
template<int CO, int TPN>
__global__ void __launch_bounds__(32 * TPN) edge_nnconv_kernel(
        const int* __restrict__ off, const int* __restrict__ sdst,
        const float* __restrict__ sea,
        const float* __restrict__ T, const float* __restrict__ Tb,
        float* __restrict__ agg) {
    int t = threadIdx.x;
    int g = t / TPN;
    int o0 = (t - g * TPN) * 4;
    int n = blockIdx.x * 32 + g;

    int beg = off[n], end = off[n + 1];
    if (beg == end) return;

    const float4* tp = reinterpret_cast<const float4*>(T + (n * CO + o0) * 8);
    float4 T0 = tp[0], T1 = tp[1], T2 = tp[2], T3 = tp[3];
    float4 T4 = tp[4], T5 = tp[5], T6 = tp[6], T7 = tp[7];
    float4 bb = *reinterpret_cast<const float4*>(Tb + n * CO + o0);

    for (int e = beg; e < end; e++) {
        int dst = sdst[e];
        const float4* eap = reinterpret_cast<const float4*>(sea + e * 8);
        float4 a0 = eap[0], a1 = eap[1];
        float r0 = bb.x + a0.x * T0.x + a0.y * T0.y + a0.z * T0.z + a0.w * T0.w
                        + a1.x * T1.x + a1.y * T1.y + a1.z * T1.z + a1.w * T1.w;
        float r1 = bb.y + a0.x * T2.x + a0.y * T2.y + a0.z * T2.z + a0.w * T2.w
                        + a1.x * T3.x + a1.y * T3.y + a1.z * T3.z + a1.w * T3.w;
        float r2 = bb.z + a0.x * T4.x + a0.y * T4.y + a0.z * T4.z + a0.w * T4.w
                        + a1.x * T5.x + a1.y * T5.y + a1.z * T5.z + a1.w * T5.w;
        float r3 = bb.w + a0.x * T6.x + a0.y * T6.y + a0.z * T6.z + a0.w * T6.w
                        + a1.x * T7.x + a1.y * T7.y + a1.z * T7.z + a1.w * T7.w;
        red_add_v4(agg + dst * CO + o0, r0, r1, r2, r3);
    }
}

// ---------------- H = relu(agg + X @ root + bias) ---------------------------
template<int K, int CO>
__global__ void root_relu_kernel(const float* __restrict__ agg, const float* __restrict__ X,
                                 const float* __restrict__ root, const float* __restrict__ bias,
                                 float* __restrict__ H) {
    constexpr int NB = 16;
    constexpr int ITEMS = NB * CO / 256;
    __shared__ float xs[NB][K];
    int n0 = blockIdx.x * NB;
    for (int idx = threadIdx.x; idx < NB * K; idx += 256)
        xs[idx / K][idx % K] = X[n0 * K + idx];
    __syncthreads();
#pragma unroll
    for (int j = 0; j < ITEMS; j++) {
        int item = threadIdx.x + j * 256;
        int nl = item / CO, o = item - nl * CO;
        float acc = agg[(n0 + nl) * CO + o] + bias[o];
#pragma unroll 4
        for (int i = 0; i < K; i++) acc += xs[nl][i] * root[i * CO + o];
        H[(n0 + nl) * CO + o] = fmaxf(acc, 0.f);
    }
}

// ---------------- fused: h2 = relu(...); hm = h2@muw; hl = h2@lsw -----------
__global__ void root2_heads_kernel(const float* __restrict__ agg, const float* __restrict__ H1,
                                   const float* __restrict__ root, const float* __restrict__ bias,
                                   const float* __restrict__ muw, const float* __restrict__ lsw,
                                   float* __restrict__ hm, float* __restrict__ hl) {
    __shared__ float xs[16][48];
    __shared__ float hs[16][32];
    int n0 = blockIdx.x * 16;
    for (int idx = threadIdx.x; idx < 16 * 48; idx += 256)
        xs[idx / 48][idx % 48] = H1[n0 * 48 + idx];
    __syncthreads();
#pragma unroll
    for (int j = 0; j < 2; j++) {
        int item = threadIdx.x + j * 256;
        int nl = item >> 5, o = item & 31;
        float acc = agg[(n0 + nl) * 32 + o] + bias[o];
#pragma unroll 4
        for (int i = 0; i < 48; i++) acc += xs[nl][i] * root[i * 32 + o];
        hs[nl][o] = fmaxf(acc, 0.f);
    }
    __syncthreads();
#pragma unroll
    for (int j = 0; j < 2; j++) {
        int item = threadIdx.x + j * 256;
        int nl = item >> 5;
        int r = item & 31;
        int head = r >> 4, o = r & 15;
        const float* W = head ? lsw : muw;
        float acc = 0.f;
#pragma unroll
        for (int i = 0; i < 32; i++) acc += hs[nl][i] * W[i * 16 + o];
        (head ? hl : hm)[(n0 + nl) * 16 + o] = acc;
    }
}

// ---------------- GCN scatter: node-parallel over src-CSR -------------------
__global__ void __launch_bounds__(256) gcn_edge_kernel(
        const int* __restrict__ off, const int* __restrict__ sdst,
        const float* __restrict__ hm, const float* __restrict__ hl,
        const float* __restrict__ dinv,
        float* __restrict__ aggm, float* __restrict__ aggl) {
    int t = threadIdx.x;
    int g = t >> 3;
    int r = t & 7;
    int head = r >> 2, q = r & 3;
    int n = blockIdx.x * 32 + g;
    int beg = off[n], end = off[n + 1];
    if (beg == end) return;

    const float* h = head ? hl : hm;
    float* a = head ? aggl : aggm;
    float4 v = *reinterpret_cast<const float4*>(h + n * 16 + q * 4);
    float ds = dinv[n];
    for (int e = beg; e < end; e++) {
        int dst = sdst[e];
        float w = ds * dinv[dst];
        red_add_v4(a + dst * 16 + q * 4, v.x * w, v.y * w, v.z * w, v.w * w);
    }
}

// ---------------- final: out = agg + h*invdeg + bias (mu then ls) -----------
__global__ void out_kernel(const float* __restrict__ aggm, const float* __restrict__ aggl,
                           const float* __restrict__ hm, const float* __restrict__ hl,
                           const float* __restrict__ invdeg, const float* __restrict__ mub,
                           const float* __restrict__ lsb, float* __restrict__ out) {
    int i4 = blockIdx.x * 256 + threadIdx.x;
    int n = i4 >> 2, q = i4 & 3;
    float iv = invdeg[n];
    float4* out4 = reinterpret_cast<float4*>(out);
    float4 am = reinterpret_cast<const float4*>(aggm)[i4];
    float4 vm = reinterpret_cast<const float4*>(hm)[i4];
    float4 bm = reinterpret_cast<const float4*>(mub)[q];
    out4[i4] = make_float4(am.x + vm.x * iv + bm.x, am.y + vm.y * iv + bm.y,
                           am.z + vm.z * iv + bm.z, am.w + vm.w * iv + bm.w);
    float4 al = reinterpret_cast<const float4*>(aggl)[i4];
    float4 vl = reinterpret_cast<const float4*>(hl)[i4];
    float4 bl = reinterpret_cast<const float4*>(lsb)[q];
    out4[32768 + i4] = make_float4(al.x + vl.x * iv + bl.x, al.y + vl.y * iv + bl.y,
                                   al.z + vl.z * iv + bl.z, al.w + vl.w * iv + bl.w);
}

// ---------------- launcher --------------------------------------------------
extern "C" void kernel_launch(void* const* d_in, const int* in_sizes, int n_in,
                              void* d_out, int out_size) {
    const float* x      = (const float*)d_in[0];
    const int*   ei     = (const int*)  d_in[1];
    const float* ea     = (const float*)d_in[2];
    const float* nn1_w  = (const float*)d_in[3];
    const float* nn1_b  = (const float*)d_in[4];
    const float* root1  = (const float*)d_in[5];
    const float* bias1  = (const float*)d_in[6];
    const float* nn2_w  = (const float*)d_in[7];
    const float* nn2_b  = (const float*)d_in[8];
    const float* root2  = (const float*)d_in[9];
    const float* bias2  = (const float*)d_in[10];
    const float* mu_w   = (const float*)d_in[11];
    const float* mu_b   = (const float*)d_in[12];
    const float* ls_w   = (const float*)d_in[13];
    const float* ls_b   = (const float*)d_in[14];
    float* out = (float*)d_out;

    void *pz, *pT1, *pTb1, *pT2, *pTb2, *ph1, *phm, *phl;
    void *pWtp1, *pWtp2, *pdinv, *pinvdeg, *poff, *pcur, *psdst, *psea;
    cudaGetSymbolAddress(&pz, g_zbuf);
    cudaGetSymbolAddress(&pT1, g_T1);
    cudaGetSymbolAddress(&pTb1, g_Tb1);
    cudaGetSymbolAddress(&pT2, g_T2);
    cudaGetSymbolAddress(&pTb2, g_Tb2);
    cudaGetSymbolAddress(&ph1, g_h1);
    cudaGetSymbolAddress(&phm, g_hm);
    cudaGetSymbolAddress(&phl, g_hl);
    cudaGetSymbolAddress(&pWtp1, g_Wtp1);
    cudaGetSymbolAddress(&pWtp2, g_Wtp2);
    cudaGetSymbolAddress(&pdinv, g_dinv);
    cudaGetSymbolAddress(&pinvdeg, g_invdeg);
    cudaGetSymbolAddress(&poff, g_off);
    cudaGetSymbolAddress(&pcur, g_cursor);
    cudaGetSymbolAddress(&psdst, g_sdst);
    cudaGetSymbolAddress(&psea, g_sea);

    float* zb = (float*)pz;
    int*   deg    = (int*)(zb + OFF_DEG);
    int*   outcnt = (int*)(zb + OFF_OUTCNT);
    float* agg1   = zb + OFF_AGG1;
    float* agg2   = zb + OFF_AGG2;
    float* aggm   = zb + OFF_AGGM;
    float* aggl   = zb + OFF_AGGL;

    cudaMemsetAsync(pz, 0, ZFLOATS * sizeof(float), 0);

    prep_kernel<<<418, 256>>>(ei, nn1_w, nn1_b, nn2_w, nn2_b,
                              outcnt, deg, (float*)pWtp1, (float*)pWtp2);
    scan_dinv_kernel<<<9, 1024>>>(outcnt, deg, (int*)poff, (int*)pcur,
                                  (float*)pdinv, (float*)pinvdeg);
    perm_kernel<<<256, 256>>>(ei, ea, (int*)pcur, (int*)psdst, (float*)psea);

    // layer 1
    node_gemm_kernel<64, 48><<<dim3(4, 128), 256>>>(
        x, (float*)pWtp1, (float*)pT1, (float*)pTb1);
    edge_nnconv_kernel<48, 12><<<NN / 32, 384>>>((int*)poff, (int*)psdst, (float*)psea,
                                                 (float*)pT1, (float*)pTb1, agg1);
    root_relu_kernel<64, 48><<<NN / 16, 256>>>(agg1, x, root1, bias1, (float*)ph1);

    // layer 2
    node_gemm_kernel<48, 32><<<dim3(3, 128), 256>>>(
        (float*)ph1, (float*)pWtp2, (float*)pT2, (float*)pTb2);
    edge_nnconv_kernel<32, 8><<<NN / 32, 256>>>((int*)poff, (int*)psdst, (float*)psea,
                                                (float*)pT2, (float*)pTb2, agg2);
    root2_heads_kernel<<<NN / 16, 256>>>(agg2, (float*)ph1, root2, bias2,
                                         mu_w, ls_w, (float*)phm, (float*)phl);

    // GCN scatter + output
    gcn_edge_kernel<<<NN / 32, 256>>>((int*)poff, (int*)psdst, (float*)phm, (float*)phl,
                                      (float*)pdinv, aggm, aggl);
    out_kernel<<<128, 256>>>(aggm, aggl, (float*)phm, (float*)phl,
                             (float*)pinvdeg, mu_b, ls_b, out);
}

// round 9
// speedup vs baseline: 1.5168x; 1.5168x over previous
#include <cuda_runtime.h>
#include <cstdint>

#define NN 8192
#define NE 65536

typedef unsigned long long ull;

// ---------------- zeroed scratch blob (single memset) -----------------------
#define OFF_DEG    0
#define OFF_OUTCNT 8192
#define OFF_AGG1   16384
#define OFF_AGG2   409600
#define OFF_AGGM   671744
#define OFF_AGGL   802816
#define ZFLOATS    933888
__device__ __align__(16) float g_zbuf[ZFLOATS];

// ---------------- other scratch ---------------------------------------------
__device__ __align__(16) float g_T1[NN * 48 * 8];
__device__ __align__(16) float g_Tb1[NN * 48];
__device__ __align__(16) float g_T2[NN * 32 * 8];
__device__ __align__(16) float g_Tb2[NN * 32];
__device__ __align__(16) float g_h1[NN * 48];
__device__ __align__(16) float g_hm[NN * 16];
__device__ __align__(16) float g_hl[NN * 16];
__device__ __align__(16) float g_sea[NE * 8];   // edge_attr in src-sorted order
__device__ int   g_sdst[NE];                    // dst in src-sorted order
__device__ int   g_off[NN + 1];                 // CSR offsets by src
__device__ int   g_cursor[NN];
// Wt layout: Wt[i*NC + c]; c<8*CO: o=c>>3,s=c&7 -> nn_w[s*(K*CO)+i*CO+o]; else bias col
__device__ __align__(16) float g_Wt1[64 * 432];
__device__ __align__(16) float g_Wt2[48 * 288];
__device__ float g_dinv[NN];
__device__ float g_invdeg[NN];

__device__ __forceinline__ void red_add_v4(float* p, float a, float b, float c, float d) {
    asm volatile("red.global.add.v4.f32 [%0], {%1,%2,%3,%4};"
                 :: "l"(p), "f"(a), "f"(b), "f"(c), "f"(d) : "memory");
}

__device__ __forceinline__ uint32_t f2tf32(float f) {
    uint32_t r;
    asm("cvt.rna.tf32.f32 %0, %1;" : "=r"(r) : "f"(f));
    return r;
}

__device__ __forceinline__ void mma_tf32(float* c, const uint32_t* a, const uint32_t* b) {
    asm("mma.sync.aligned.m16n8k8.row.col.f32.tf32.tf32.f32 "
        "{%0,%1,%2,%3}, {%4,%5,%6,%7}, {%8,%9}, {%0,%1,%2,%3};"
        : "+f"(c[0]), "+f"(c[1]), "+f"(c[2]), "+f"(c[3])
        : "r"(a[0]), "r"(a[1]), "r"(a[2]), "r"(a[3]), "r"(b[0]), "r"(b[1]));
}

// ---------------- prep: degree/outdeg counts + weight transposes ------------
__global__ void prep_kernel(const int* __restrict__ ei,
                            const float* __restrict__ nn1w, const float* __restrict__ nn1b,
                            const float* __restrict__ nn2w, const float* __restrict__ nn2b,
                            int* __restrict__ outcnt, int* __restrict__ deg,
                            float* __restrict__ Wt1, float* __restrict__ Wt2) {
    int bx = blockIdx.x, t = threadIdx.x;
    if (bx < 256) {
        int e = bx * 256 + t;
        atomicAdd(&outcnt[ei[e]], 1);
        atomicAdd(&deg[ei[NE + e]], 1);
    } else if (bx < 364) {               // 27648: K=64, CO=48, NC=432
        int idx = (bx - 256) * 256 + t;
        int i = idx / 432, c = idx - i * 432;
        float v;
        if (c < 384) { int o = c >> 3, s = c & 7; v = nn1w[s * 3072 + i * 48 + o]; }
        else         { int o = c - 384;           v = nn1b[i * 48 + o]; }
        Wt1[idx] = v;
    } else {                              // 13824: K=48, CO=32, NC=288
        int idx = (bx - 364) * 256 + t;
        if (idx < 13824) {
            int i = idx / 288, c = idx - i * 288;
            float v;
            if (c < 256) { int o = c >> 3, s = c & 7; v = nn2w[s * 1536 + i * 32 + o]; }
            else         { int o = c - 256;           v = nn2b[i * 32 + o]; }
            Wt2[idx] = v;
        }
    }
}

// ---------------- block 0: exclusive scan of outcnt; blocks 1..8: dinv ------
__global__ void scan_dinv_kernel(const int* __restrict__ outcnt, const int* __restrict__ deg,
                                 int* __restrict__ off, int* __restrict__ cursor,
                                 float* __restrict__ dinv, float* __restrict__ invdeg) {
    int t = threadIdx.x;
    if (blockIdx.x == 0) {
        __shared__ int wsum[32];
        int base = t * 8;
        int v[8];
        int s = 0;
#pragma unroll
        for (int j = 0; j < 8; j++) { v[j] = outcnt[base + j]; s += v[j]; }
        int lane = t & 31, wid = t >> 5;
        int inc = s;
#pragma unroll
        for (int d = 1; d < 32; d <<= 1) {
            int n = __shfl_up_sync(0xFFFFFFFFu, inc, d);
            if (lane >= d) inc += n;
        }
        int excl_warp = inc - s;
        if (lane == 31) wsum[wid] = inc;
        __syncthreads();
        if (t < 32) {
            int w = wsum[t];
            int wi = w;
#pragma unroll
            for (int d = 1; d < 32; d <<= 1) {
                int n = __shfl_up_sync(0xFFFFFFFFu, wi, d);
                if (t >= d) wi += n;
            }
            wsum[t] = wi - w;
        }
        __syncthreads();
        int run = wsum[wid] + excl_warp;
#pragma unroll
        for (int j = 0; j < 8; j++) {
            off[base + j] = run;
            cursor[base + j] = run;
            run += v[j];
        }
        if (t == 1023) off[NN] = NE;
    } else {
        int n = (blockIdx.x - 1) * 1024 + t;
        float d = (float)deg[n] + 1.0f;
        dinv[n] = rsqrtf(d);
        invdeg[n] = 1.0f / d;
    }
}

// ---------------- scatter edge payloads into src-sorted order ---------------
__global__ void perm_kernel(const int* __restrict__ ei, const float* __restrict__ ea,
                            int* __restrict__ cursor,
                            int* __restrict__ sdst, float* __restrict__ sea) {
    int e = blockIdx.x * 256 + threadIdx.x;
    int s = ei[e];
    int pos = atomicAdd(&cursor[s], 1);
    sdst[pos] = ei[NE + e];
    const float4* ev = reinterpret_cast<const float4*>(ea + e * 8);
    float4* sv = reinterpret_cast<float4*>(sea + pos * 8);
    sv[0] = ev[0];
    sv[1] = ev[1];
}

// ---------------- node GEMM on tensor cores: 3xTF32 mma (fp32 accuracy) -----
// Block: 128 thr (4 warps). Tile: 64 rows x 128 cols. Warp: 16 rows x 128 cols.
// Xs padded to stride K+4, Ws to 132 -> both fragment LDS patterns conflict-free.
template<int K, int CO>
__global__ void __launch_bounds__(128) node_gemm_kernel(
        const float* __restrict__ X, const float* __restrict__ Wt,
        float* __restrict__ T, float* __restrict__ Tb) {
    constexpr int NC = CO * 9;
    constexpr int XP = K + 4;     // Xs row stride
    constexpr int WP = 132;       // Ws row stride
    constexpr int KS = K / 8;     // k-steps
    __shared__ float Xs[64 * XP];
    __shared__ float Ws[K * WP];
    int tid = threadIdx.x;
    int n0 = blockIdx.y * 64;
    int cbase = blockIdx.x * 128;

    // fill Xs (row-padded), float4 per row segment
    {
        const float4* X4 = reinterpret_cast<const float4*>(X + n0 * K);
        float4* Xs4 = reinterpret_cast<float4*>(Xs);
        for (int idx = tid; idx < 64 * (K / 4); idx += 128) {
            int r = idx / (K / 4), q = idx - r * (K / 4);
            Xs4[r * (XP / 4) + q] = X4[r * (K / 4) + q];
        }
    }
    // fill Ws (zero-padded beyond NC)
    for (int idx = tid; idx < K * 128; idx += 128) {
        int k = idx >> 7, j = idx & 127;
        int c = cbase + j;
        Ws[k * WP + j] = (c < NC) ? Wt[k * NC + c] : 0.f;
    }
    __syncthreads();

    int lane = tid & 31, wp = tid >> 5;
    int gid = lane >> 2;          // 0..7
    int tig = lane & 3;           // 0..3
    int arow = wp * 16 + gid;

    float acc[16][4];
#pragma unroll
    for (int nt = 0; nt < 16; nt++)
#pragma unroll
        for (int j = 0; j < 4; j++) acc[nt][j] = 0.f;

#pragma unroll
    for (int ks = 0; ks < KS; ks++) {
        int k0 = ks * 8 + tig;
        float f0 = Xs[arow * XP + k0];
        float f1 = Xs[(arow + 8) * XP + k0];
        float f2 = Xs[arow * XP + k0 + 4];
        float f3 = Xs[(arow + 8) * XP + k0 + 4];
        uint32_t ah[4], al[4];
        ah[0] = f2tf32(f0); al[0] = f2tf32(f0 - __uint_as_float(ah[0]));
        ah[1] = f2tf32(f1); al[1] = f2tf32(f1 - __uint_as_float(ah[1]));
        ah[2] = f2tf32(f2); al[2] = f2tf32(f2 - __uint_as_float(ah[2]));
        ah[3] = f2tf32(f3); al[3] = f2tf32(f3 - __uint_as_float(ah[3]));
#pragma unroll
        for (int nt = 0; nt < 16; nt++) {
            int cb = nt * 8 + gid;
            float g0 = Ws[(ks * 8 + tig) * WP + cb];
            float g1 = Ws[(ks * 8 + tig + 4) * WP + cb];
            uint32_t bh[2], bl[2];
            bh[0] = f2tf32(g0); bl[0] = f2tf32(g0 - __uint_as_float(bh[0]));
            bh[1] = f2tf32(g1); bl[1] = f2tf32(g1 - __uint_as_float(bh[1]));
            mma_tf32(acc[nt], al, bh);
            mma_tf32(acc[nt], ah, bl);
            mma_tf32(acc[nt], ah, bh);
        }
    }

    // store: rows arow (c0,c1) and arow+8 (c2,c3), cols cbase + nt*8 + tig*2
    int r0 = n0 + arow;
#pragma unroll
    for (int nt = 0; nt < 16; nt++) {
        int c = cbase + nt * 8 + tig * 2;
        if (c < NC) {
            if (c < CO * 8) {
                T[r0 * (CO * 8) + c]           = acc[nt][0];
                T[r0 * (CO * 8) + c + 1]       = acc[nt][1];
                T[(r0 + 8) * (CO * 8) + c]     = acc[nt][2];
                T[(r0 + 8) * (CO * 8) + c + 1] = acc[nt][3];
            } else {
                int cc = c - CO * 8;
                Tb[r0 * CO + cc]           = acc[nt][0];
                Tb[r0 * CO + cc + 1]       = acc[nt][1];
                Tb[(r0 + 8) * CO + cc]     = acc[nt][2];
                Tb[(r0 + 8) * CO + cc + 1] = acc[nt][3];
            }
        }
    }
}

// ---------------- edge NNConv: node-parallel over src-CSR -------------------
template<int CO, int TPN>
__global__ void __launch_bounds__(32 * TPN) edge_nnconv_kernel(
        const int* __restrict__ off, const int* __restrict__ sdst,
        const float* __restrict__ sea,
        const float* __restrict__ T, const float* __restrict__ Tb,
        float* __restrict__ agg) {
    int t = threadIdx.x;
    int g = t / TPN;
    int o0 = (t - g * TPN) * 4;
    int n = blockIdx.x * 32 + g;

    int beg = off[n], end = off[n + 1];
    if (beg == end) return;

    const float4* tp = reinterpret_cast<const float4*>(T + (n * CO + o0) * 8);
    float4 T0 = tp[0], T1 = tp[1], T2 = tp[2], T3 = tp[3];
    float4 T4 = tp[4], T5 = tp[5], T6 = tp[6], T7 = tp[7];
    float4 bb = *reinterpret_cast<const float4*>(Tb + n * CO + o0);

    for (int e = beg; e < end; e++) {
        int dst = sdst[e];
        const float4* eap = reinterpret_cast<const float4*>(sea + e * 8);
        float4 a0 = eap[0], a1 = eap[1];
        float r0 = bb.x + a0.x * T0.x + a0.y * T0.y + a0.z * T0.z + a0.w * T0.w
                        + a1.x * T1.x + a1.y * T1.y + a1.z * T1.z + a1.w * T1.w;
        float r1 = bb.y + a0.x * T2.x + a0.y * T2.y + a0.z * T2.z + a0.w * T2.w
                        + a1.x * T3.x + a1.y * T3.y + a1.z * T3.z + a1.w * T3.w;
        float r2 = bb.z + a0.x * T4.x + a0.y * T4.y + a0.z * T4.z + a0.w * T4.w
                        + a1.x * T5.x + a1.y * T5.y + a1.z * T5.z + a1.w * T5.w;
        float r3 = bb.w + a0.x * T6.x + a0.y * T6.y + a0.z * T6.z + a0.w * T6.w
                        + a1.x * T7.x + a1.y * T7.y + a1.z * T7.z + a1.w * T7.w;
        red_add_v4(agg + dst * CO + o0, r0, r1, r2, r3);
    }
}

// ---------------- H = relu(agg + X @ root + bias) ---------------------------
template<int K, int CO>
__global__ void root_relu_kernel(const float* __restrict__ agg, const float* __restrict__ X,
                                 const float* __restrict__ root, const float* __restrict__ bias,
                                 float* __restrict__ H) {
    constexpr int NB = 16;
    constexpr int ITEMS = NB * CO / 256;
    __shared__ float xs[NB][K];
    int n0 = blockIdx.x * NB;
    for (int idx = threadIdx.x; idx < NB * K; idx += 256)
        xs[idx / K][idx % K] = X[n0 * K + idx];
    __syncthreads();
#pragma unroll
    for (int j = 0; j < ITEMS; j++) {
        int item = threadIdx.x + j * 256;
        int nl = item / CO, o = item - nl * CO;
        float acc = agg[(n0 + nl) * CO + o] + bias[o];
#pragma unroll 4
        for (int i = 0; i < K; i++) acc += xs[nl][i] * root[i * CO + o];
        H[(n0 + nl) * CO + o] = fmaxf(acc, 0.f);
    }
}

// ---------------- fused: h2 = relu(...); hm = h2@muw; hl = h2@lsw -----------
__global__ void root2_heads_kernel(const float* __restrict__ agg, const float* __restrict__ H1,
                                   const float* __restrict__ root, const float* __restrict__ bias,
                                   const float* __restrict__ muw, const float* __restrict__ lsw,
                                   float* __restrict__ hm, float* __restrict__ hl) {
    __shared__ float xs[16][48];
    __shared__ float hs[16][32];
    int n0 = blockIdx.x * 16;
    for (int idx = threadIdx.x; idx < 16 * 48; idx += 256)
        xs[idx / 48][idx % 48] = H1[n0 * 48 + idx];
    __syncthreads();
#pragma unroll
    for (int j = 0; j < 2; j++) {
        int item = threadIdx.x + j * 256;
        int nl = item >> 5, o = item & 31;
        float acc = agg[(n0 + nl) * 32 + o] + bias[o];
#pragma unroll 4
        for (int i = 0; i < 48; i++) acc += xs[nl][i] * root[i * 32 + o];
        hs[nl][o] = fmaxf(acc, 0.f);
    }
    __syncthreads();
#pragma unroll
    for (int j = 0; j < 2; j++) {
        int item = threadIdx.x + j * 256;
        int nl = item >> 5;
        int r = item & 31;
        int head = r >> 4, o = r & 15;
        const float* W = head ? lsw : muw;
        float acc = 0.f;
#pragma unroll
        for (int i = 0; i < 32; i++) acc += hs[nl][i] * W[i * 16 + o];
        (head ? hl : hm)[(n0 + nl) * 16 + o] = acc;
    }
}

// ---------------- GCN scatter: node-parallel over src-CSR -------------------
__global__ void __launch_bounds__(256) gcn_edge_kernel(
        const int* __restrict__ off, const int* __restrict__ sdst,
        const float* __restrict__ hm, const float* __restrict__ hl,
        const float* __restrict__ dinv,
        float* __restrict__ aggm, float* __restrict__ aggl) {
    int t = threadIdx.x;
    int g = t >> 3;
    int r = t & 7;
    int head = r >> 2, q = r & 3;
    int n = blockIdx.x * 32 + g;
    int beg = off[n], end = off[n + 1];
    if (beg == end) return;

    const float* h = head ? hl : hm;
    float* a = head ? aggl : aggm;
    float4 v = *reinterpret_cast<const float4*>(h + n * 16 + q * 4);
    float ds = dinv[n];
    for (int e = beg; e < end; e++) {
        int dst = sdst[e];
        float w = ds * dinv[dst];
        red_add_v4(a + dst * 16 + q * 4, v.x * w, v.y * w, v.z * w, v.w * w);
    }
}

// ---------------- final: out = agg + h*invdeg + bias (mu then ls) -----------
__global__ void out_kernel(const float* __restrict__ aggm, const float* __restrict__ aggl,
                           const float* __restrict__ hm, const float* __restrict__ hl,
                           const float* __restrict__ invdeg, const float* __restrict__ mub,
                           const float* __restrict__ lsb, float* __restrict__ out) {
    int i4 = blockIdx.x * 256 + threadIdx.x;
    int n = i4 >> 2, q = i4 & 3;
    float iv = invdeg[n];
    float4* out4 = reinterpret_cast<float4*>(out);
    float4 am = reinterpret_cast<const float4*>(aggm)[i4];
    float4 vm = reinterpret_cast<const float4*>(hm)[i4];
    float4 bm = reinterpret_cast<const float4*>(mub)[q];
    out4[i4] = make_float4(am.x + vm.x * iv + bm.x, am.y + vm.y * iv + bm.y,
                           am.z + vm.z * iv + bm.z, am.w + vm.w * iv + bm.w);
    float4 al = reinterpret_cast<const float4*>(aggl)[i4];
    float4 vl = reinterpret_cast<const float4*>(hl)[i4];
    float4 bl = reinterpret_cast<const float4*>(lsb)[q];
    out4[32768 + i4] = make_float4(al.x + vl.x * iv + bl.x, al.y + vl.y * iv + bl.y,
                                   al.z + vl.z * iv + bl.z, al.w + vl.w * iv + bl.w);
}

// ---------------- launcher --------------------------------------------------
extern "C" void kernel_launch(void* const* d_in, const int* in_sizes, int n_in,
                              void* d_out, int out_size) {
    const float* x      = (const float*)d_in[0];
    const int*   ei     = (const int*)  d_in[1];
    const float* ea     = (const float*)d_in[2];
    const float* nn1_w  = (const float*)d_in[3];
    const float* nn1_b  = (const float*)d_in[4];
    const float* root1  = (const float*)d_in[5];
    const float* bias1  = (const float*)d_in[6];
    const float* nn2_w  = (const float*)d_in[7];
    const float* nn2_b  = (const float*)d_in[8];
    const float* root2  = (const float*)d_in[9];
    const float* bias2  = (const float*)d_in[10];
    const float* mu_w   = (const float*)d_in[11];
    const float* mu_b   = (const float*)d_in[12];
    const float* ls_w   = (const float*)d_in[13];
    const float* ls_b   = (const float*)d_in[14];
    float* out = (float*)d_out;

    void *pz, *pT1, *pTb1, *pT2, *pTb2, *ph1, *phm, *phl;
    void *pWt1, *pWt2, *pdinv, *pinvdeg, *poff, *pcur, *psdst, *psea;
    cudaGetSymbolAddress(&pz, g_zbuf);
    cudaGetSymbolAddress(&pT1, g_T1);
    cudaGetSymbolAddress(&pTb1, g_Tb1);
    cudaGetSymbolAddress(&pT2, g_T2);
    cudaGetSymbolAddress(&pTb2, g_Tb2);
    cudaGetSymbolAddress(&ph1, g_h1);
    cudaGetSymbolAddress(&phm, g_hm);
    cudaGetSymbolAddress(&phl, g_hl);
    cudaGetSymbolAddress(&pWt1, g_Wt1);
    cudaGetSymbolAddress(&pWt2, g_Wt2);
    cudaGetSymbolAddress(&pdinv, g_dinv);
    cudaGetSymbolAddress(&pinvdeg, g_invdeg);
    cudaGetSymbolAddress(&poff, g_off);
    cudaGetSymbolAddress(&pcur, g_cursor);
    cudaGetSymbolAddress(&psdst, g_sdst);
    cudaGetSymbolAddress(&psea, g_sea);

    float* zb = (float*)pz;
    int*   deg    = (int*)(zb + OFF_DEG);
    int*   outcnt = (int*)(zb + OFF_OUTCNT);
    float* agg1   = zb + OFF_AGG1;
    float* agg2   = zb + OFF_AGG2;
    float* aggm   = zb + OFF_AGGM;
    float* aggl   = zb + OFF_AGGL;

    cudaMemsetAsync(pz, 0, ZFLOATS * sizeof(float), 0);

    prep_kernel<<<418, 256>>>(ei, nn1_w, nn1_b, nn2_w, nn2_b,
                              outcnt, deg, (float*)pWt1, (float*)pWt2);
    scan_dinv_kernel<<<9, 1024>>>(outcnt, deg, (int*)poff, (int*)pcur,
                                  (float*)pdinv, (float*)pinvdeg);
    perm_kernel<<<256, 256>>>(ei, ea, (int*)pcur, (int*)psdst, (float*)psea);

    // layer 1
    node_gemm_kernel<64, 48><<<dim3(4, 128), 128>>>(
        x, (float*)pWt1, (float*)pT1, (float*)pTb1);
    edge_nnconv_kernel<48, 12><<<NN / 32, 384>>>((int*)poff, (int*)psdst, (float*)psea,
                                                 (float*)pT1, (float*)pTb1, agg1);
    root_relu_kernel<64, 48><<<NN / 16, 256>>>(agg1, x, root1, bias1, (float*)ph1);

    // layer 2
    node_gemm_kernel<48, 32><<<dim3(3, 128), 128>>>(
        (float*)ph1, (float*)pWt2, (float*)pT2, (float*)pTb2);
    edge_nnconv_kernel<32, 8><<<NN / 32, 256>>>((int*)poff, (int*)psdst, (float*)psea,
                                                (float*)pT2, (float*)pTb2, agg2);
    root2_heads_kernel<<<NN / 16, 256>>>(agg2, (float*)ph1, root2, bias2,
                                         mu_w, ls_w, (float*)phm, (float*)phl);

    // GCN scatter + output
    gcn_edge_kernel<<<NN / 32, 256>>>((int*)poff, (int*)psdst, (float*)phm, (float*)phl,
                                      (float*)pdinv, aggm, aggl);
    out_kernel<<<128, 256>>>(aggm, aggl, (float*)phm, (float*)phl,
                             (float*)pinvdeg, mu_b, ls_b, out);
}

// round 10
// speedup vs baseline: 1.5822x; 1.0431x over previous
#include <cuda_runtime.h>
#include <cstdint>

#define NN 8192
#define NE 65536

typedef unsigned long long ull;

// ---------------- zeroed scratch blob (single memset) -----------------------
#define OFF_DEG    0
#define OFF_OUTCNT 8192
#define OFF_AGG1   16384
#define OFF_AGG2   409600
#define OFF_AGGM   671744
#define OFF_AGGL   802816
#define ZFLOATS    933888
__device__ __align__(16) float g_zbuf[ZFLOATS];

// ---------------- other scratch ---------------------------------------------
__device__ __align__(16) float g_T1[NN * 48 * 8];
__device__ __align__(16) float g_Tb1[NN * 48];
__device__ __align__(16) float g_T2[NN * 32 * 8];
__device__ __align__(16) float g_Tb2[NN * 32];
__device__ __align__(16) float g_h1[NN * 48];
__device__ __align__(16) float g_hm[NN * 16];
__device__ __align__(16) float g_hl[NN * 16];
__device__ __align__(16) float g_sea[NE * 8];   // edge_attr in src-sorted order
__device__ int   g_sdst[NE];                    // dst in src-sorted order
__device__ int   g_off[NN + 1];                 // CSR offsets by src
__device__ int   g_cursor[NN];
// pre-split TF32 weights: {hi, lo} per element, layout [k][c] (c as in Wt)
__device__ __align__(16) uint2 g_Whl1[64 * 432];
__device__ __align__(16) uint2 g_Whl2[48 * 288];
__device__ float g_dinv[NN];
__device__ float g_invdeg[NN];

__device__ __forceinline__ void red_add_v4(float* p, float a, float b, float c, float d) {
    asm volatile("red.global.add.v4.f32 [%0], {%1,%2,%3,%4};"
                 :: "l"(p), "f"(a), "f"(b), "f"(c), "f"(d) : "memory");
}

__device__ __forceinline__ uint32_t f2tf32(float f) {
    uint32_t r;
    asm("cvt.rna.tf32.f32 %0, %1;" : "=r"(r) : "f"(f));
    return r;
}

__device__ __forceinline__ void mma_tf32(float* c, const uint32_t* a, const uint32_t* b) {
    asm("mma.sync.aligned.m16n8k8.row.col.f32.tf32.tf32.f32 "
        "{%0,%1,%2,%3}, {%4,%5,%6,%7}, {%8,%9}, {%0,%1,%2,%3};"
        : "+f"(c[0]), "+f"(c[1]), "+f"(c[2]), "+f"(c[3])
        : "r"(a[0]), "r"(a[1]), "r"(a[2]), "r"(a[3]), "r"(b[0]), "r"(b[1]));
}

// ---------------- prep: degree/outdeg counts + pre-split TF32 weights -------
__global__ void prep_kernel(const int* __restrict__ ei,
                            const float* __restrict__ nn1w, const float* __restrict__ nn1b,
                            const float* __restrict__ nn2w, const float* __restrict__ nn2b,
                            int* __restrict__ outcnt, int* __restrict__ deg,
                            uint2* __restrict__ Whl1, uint2* __restrict__ Whl2) {
    int bx = blockIdx.x, t = threadIdx.x;
    if (bx < 256) {
        int e = bx * 256 + t;
        atomicAdd(&outcnt[ei[e]], 1);
        atomicAdd(&deg[ei[NE + e]], 1);
    } else if (bx < 364) {               // 27648: K=64, CO=48, NC=432
        int idx = (bx - 256) * 256 + t;
        int i = idx / 432, c = idx - i * 432;
        float v;
        if (c < 384) { int o = c >> 3, s = c & 7; v = nn1w[s * 3072 + i * 48 + o]; }
        else         { int o = c - 384;           v = nn1b[i * 48 + o]; }
        uint32_t hi = f2tf32(v);
        Whl1[idx] = make_uint2(hi, f2tf32(v - __uint_as_float(hi)));
    } else {                              // 13824: K=48, CO=32, NC=288
        int idx = (bx - 364) * 256 + t;
        if (idx < 13824) {
            int i = idx / 288, c = idx - i * 288;
            float v;
            if (c < 256) { int o = c >> 3, s = c & 7; v = nn2w[s * 1536 + i * 32 + o]; }
            else         { int o = c - 256;           v = nn2b[i * 32 + o]; }
            uint32_t hi = f2tf32(v);
            Whl2[idx] = make_uint2(hi, f2tf32(v - __uint_as_float(hi)));
        }
    }
}

// ---------------- block 0: exclusive scan of outcnt; blocks 1..8: dinv ------
__global__ void scan_dinv_kernel(const int* __restrict__ outcnt, const int* __restrict__ deg,
                                 int* __restrict__ off, int* __restrict__ cursor,
                                 float* __restrict__ dinv, float* __restrict__ invdeg) {
    int t = threadIdx.x;
    if (blockIdx.x == 0) {
        __shared__ int wsum[32];
        int base = t * 8;
        int v[8];
        int s = 0;
#pragma unroll
        for (int j = 0; j < 8; j++) { v[j] = outcnt[base + j]; s += v[j]; }
        int lane = t & 31, wid = t >> 5;
        int inc = s;
#pragma unroll
        for (int d = 1; d < 32; d <<= 1) {
            int n = __shfl_up_sync(0xFFFFFFFFu, inc, d);
            if (lane >= d) inc += n;
        }
        int excl_warp = inc - s;
        if (lane == 31) wsum[wid] = inc;
        __syncthreads();
        if (t < 32) {
            int w = wsum[t];
            int wi = w;
#pragma unroll
            for (int d = 1; d < 32; d <<= 1) {
                int n = __shfl_up_sync(0xFFFFFFFFu, wi, d);
                if (t >= d) wi += n;
            }
            wsum[t] = wi - w;
        }
        __syncthreads();
        int run = wsum[wid] + excl_warp;
#pragma unroll
        for (int j = 0; j < 8; j++) {
            off[base + j] = run;
            cursor[base + j] = run;
            run += v[j];
        }
        if (t == 1023) off[NN] = NE;
    } else {
        int n = (blockIdx.x - 1) * 1024 + t;
        float d = (float)deg[n] + 1.0f;
        dinv[n] = rsqrtf(d);
        invdeg[n] = 1.0f / d;
    }
}

// ---------------- scatter edge payloads into src-sorted order ---------------
__global__ void perm_kernel(const int* __restrict__ ei, const float* __restrict__ ea,
                            int* __restrict__ cursor,
                            int* __restrict__ sdst, float* __restrict__ sea) {
    int e = blockIdx.x * 256 + threadIdx.x;
    int s = ei[e];
    int pos = atomicAdd(&cursor[s], 1);
    sdst[pos] = ei[NE + e];
    const float4* ev = reinterpret_cast<const float4*>(ea + e * 8);
    float4* sv = reinterpret_cast<float4*>(sea + pos * 8);
    sv[0] = ev[0];
    sv[1] = ev[1];
}

// ---------------- node GEMM: TF32 mma, B pre-split (hi,lo) in smem ----------
// Block: 256 thr (8 warps). Tile: 128 rows x 64 cols. Warp: 16 rows.
// Per k-step per n-tile: 2x LDS.64 (uint2 {hi,lo}) + 3 MMA; A split at runtime.
template<int K, int CO>
__global__ void __launch_bounds__(256) node_gemm_kernel(
        const float* __restrict__ X, const uint2* __restrict__ Whl,
        float* __restrict__ T, float* __restrict__ Tb) {
    constexpr int NC = CO * 9;
    constexpr int XP = K + 4;     // Xs row stride (floats)
    constexpr int WP2 = 68;       // Ws2 row stride (uint2)
    constexpr int KS = K / 8;
    extern __shared__ char smem_raw[];
    float* Xs  = reinterpret_cast<float*>(smem_raw);                 // [128][XP]
    uint2* Ws2 = reinterpret_cast<uint2*>(smem_raw + 128 * XP * 4);  // [K][WP2]
    int tid = threadIdx.x;
    int n0 = blockIdx.y * 128;
    int cbase = blockIdx.x * 64;

    // fill Xs (row-padded)
    {
        const float4* X4 = reinterpret_cast<const float4*>(X + n0 * K);
        float4* Xs4 = reinterpret_cast<float4*>(Xs);
        for (int idx = tid; idx < 128 * (K / 4); idx += 256) {
            int r = idx / (K / 4), q = idx - r * (K / 4);
            Xs4[r * (XP / 4) + q] = X4[r * (K / 4) + q];
        }
    }
    // fill Ws2 (zero-padded beyond NC)
    for (int idx = tid; idx < K * 64; idx += 256) {
        int k = idx >> 6, j = idx & 63;
        int c = cbase + j;
        Ws2[k * WP2 + j] = (c < NC) ? Whl[k * NC + c] : make_uint2(0u, 0u);
    }
    __syncthreads();

    int lane = tid & 31, wp = tid >> 5;
    int gid = lane >> 2;          // 0..7
    int tig = lane & 3;           // 0..3
    int arow = wp * 16 + gid;

    float acc[8][4];
#pragma unroll
    for (int nt = 0; nt < 8; nt++)
#pragma unroll
        for (int j = 0; j < 4; j++) acc[nt][j] = 0.f;

#pragma unroll
    for (int ks = 0; ks < KS; ks++) {
        int k0 = ks * 8 + tig;
        float f0 = Xs[arow * XP + k0];
        float f1 = Xs[(arow + 8) * XP + k0];
        float f2 = Xs[arow * XP + k0 + 4];
        float f3 = Xs[(arow + 8) * XP + k0 + 4];
        uint32_t ah[4], al[4];
        ah[0] = f2tf32(f0); al[0] = f2tf32(f0 - __uint_as_float(ah[0]));
        ah[1] = f2tf32(f1); al[1] = f2tf32(f1 - __uint_as_float(ah[1]));
        ah[2] = f2tf32(f2); al[2] = f2tf32(f2 - __uint_as_float(ah[2]));
        ah[3] = f2tf32(f3); al[3] = f2tf32(f3 - __uint_as_float(ah[3]));
#pragma unroll
        for (int nt = 0; nt < 8; nt++) {
            int cb = nt * 8 + gid;
            uint2 b0 = Ws2[(ks * 8 + tig) * WP2 + cb];
            uint2 b1 = Ws2[(ks * 8 + tig + 4) * WP2 + cb];
            uint32_t bh[2] = { b0.x, b1.x };
            uint32_t bl[2] = { b0.y, b1.y };
            mma_tf32(acc[nt], al, bh);
            mma_tf32(acc[nt], ah, bl);
            mma_tf32(acc[nt], ah, bh);
        }
    }

    int r0 = n0 + arow;
#pragma unroll
    for (int nt = 0; nt < 8; nt++) {
        int c = cbase + nt * 8 + tig * 2;
        if (c < NC) {
            if (c < CO * 8) {
                T[r0 * (CO * 8) + c]           = acc[nt][0];
                T[r0 * (CO * 8) + c + 1]       = acc[nt][1];
                T[(r0 + 8) * (CO * 8) + c]     = acc[nt][2];
                T[(r0 + 8) * (CO * 8) + c + 1] = acc[nt][3];
            } else {
                int cc = c - CO * 8;
                Tb[r0 * CO + cc]           = acc[nt][0];
                Tb[r0 * CO + cc + 1]       = acc[nt][1];
                Tb[(r0 + 8) * CO + cc]     = acc[nt][2];
                Tb[(r0 + 8) * CO + cc + 1] = acc[nt][3];
            }
        }
    }
}

// ---------------- edge NNConv: node-parallel over src-CSR -------------------
template<int CO, int TPN>
__global__ void __launch_bounds__(32 * TPN) edge_nnconv_kernel(
        const int* __restrict__ off, const int* __restrict__ sdst,
        const float* __restrict__ sea,
        const float* __restrict__ T, const float* __restrict__ Tb,
        float* __restrict__ agg) {
    int t = threadIdx.x;
    int g = t / TPN;
    int o0 = (t - g * TPN) * 4;
    int n = blockIdx.x * 32 + g;

    int beg = off[n], end = off[n + 1];
    if (beg == end) return;

    const float4* tp = reinterpret_cast<const float4*>(T + (n * CO + o0) * 8);
    float4 T0 = tp[0], T1 = tp[1], T2 = tp[2], T3 = tp[3];
    float4 T4 = tp[4], T5 = tp[5], T6 = tp[6], T7 = tp[7];
    float4 bb = *reinterpret_cast<const float4*>(Tb + n * CO + o0);

    for (int e = beg; e < end; e++) {
        int dst = sdst[e];
        const float4* eap = reinterpret_cast<const float4*>(sea + e * 8);
        float4 a0 = eap[0], a1 = eap[1];
        float r0 = bb.x + a0.x * T0.x + a0.y * T0.y + a0.z * T0.z + a0.w * T0.w
                        + a1.x * T1.x + a1.y * T1.y + a1.z * T1.z + a1.w * T1.w;
        float r1 = bb.y + a0.x * T2.x + a0.y * T2.y + a0.z * T2.z + a0.w * T2.w
                        + a1.x * T3.x + a1.y * T3.y + a1.z * T3.z + a1.w * T3.w;
        float r2 = bb.z + a0.x * T4.x + a0.y * T4.y + a0.z * T4.z + a0.w * T4.w
                        + a1.x * T5.x + a1.y * T5.y + a1.z * T5.z + a1.w * T5.w;
        float r3 = bb.w + a0.x * T6.x + a0.y * T6.y + a0.z * T6.z + a0.w * T6.w
                        + a1.x * T7.x + a1.y * T7.y + a1.z * T7.z + a1.w * T7.w;
        red_add_v4(agg + dst * CO + o0, r0, r1, r2, r3);
    }
}

// ---------------- H = relu(agg + X @ root + bias) ---------------------------
template<int K, int CO>
__global__ void root_relu_kernel(const float* __restrict__ agg, const float* __restrict__ X,
                                 const float* __restrict__ root, const float* __restrict__ bias,
                                 float* __restrict__ H) {
    constexpr int NB = 16;
    constexpr int ITEMS = NB * CO / 256;
    __shared__ float xs[NB][K];
    int n0 = blockIdx.x * NB;
    for (int idx = threadIdx.x; idx < NB * K; idx += 256)
        xs[idx / K][idx % K] = X[n0 * K + idx];
    __syncthreads();
#pragma unroll
    for (int j = 0; j < ITEMS; j++) {
        int item = threadIdx.x + j * 256;
        int nl = item / CO, o = item - nl * CO;
        float acc = agg[(n0 + nl) * CO + o] + bias[o];
#pragma unroll 4
        for (int i = 0; i < K; i++) acc += xs[nl][i] * root[i * CO + o];
        H[(n0 + nl) * CO + o] = fmaxf(acc, 0.f);
    }
}

// ---------------- fused: h2 = relu(...); hm = h2@muw; hl = h2@lsw -----------
__global__ void root2_heads_kernel(const float* __restrict__ agg, const float* __restrict__ H1,
                                   const float* __restrict__ root, const float* __restrict__ bias,
                                   const float* __restrict__ muw, const float* __restrict__ lsw,
                                   float* __restrict__ hm, float* __restrict__ hl) {
    __shared__ float xs[16][48];
    __shared__ float hs[16][32];
    int n0 = blockIdx.x * 16;
    for (int idx = threadIdx.x; idx < 16 * 48; idx += 256)
        xs[idx / 48][idx % 48] = H1[n0 * 48 + idx];
    __syncthreads();
#pragma unroll
    for (int j = 0; j < 2; j++) {
        int item = threadIdx.x + j * 256;
        int nl = item >> 5, o = item & 31;
        float acc = agg[(n0 + nl) * 32 + o] + bias[o];
#pragma unroll 4
        for (int i = 0; i < 48; i++) acc += xs[nl][i] * root[i * 32 + o];
        hs[nl][o] = fmaxf(acc, 0.f);
    }
    __syncthreads();
#pragma unroll
    for (int j = 0; j < 2; j++) {
        int item = threadIdx.x + j * 256;
        int nl = item >> 5;
        int r = item & 31;
        int head = r >> 4, o = r & 15;
        const float* W = head ? lsw : muw;
        float acc = 0.f;
#pragma unroll
        for (int i = 0; i < 32; i++) acc += hs[nl][i] * W[i * 16 + o];
        (head ? hl : hm)[(n0 + nl) * 16 + o] = acc;
    }
}

// ---------------- GCN scatter: node-parallel over src-CSR -------------------
__global__ void __launch_bounds__(256) gcn_edge_kernel(
        const int* __restrict__ off, const int* __restrict__ sdst,
        const float* __restrict__ hm, const float* __restrict__ hl,
        const float* __restrict__ dinv,
        float* __restrict__ aggm, float* __restrict__ aggl) {
    int t = threadIdx.x;
    int g = t >> 3;
    int r = t & 7;
    int head = r >> 2, q = r & 3;
    int n = blockIdx.x * 32 + g;
    int beg = off[n], end = off[n + 1];
    if (beg == end) return;

    const float* h = head ? hl : hm;
    float* a = head ? aggl : aggm;
    float4 v = *reinterpret_cast<const float4*>(h + n * 16 + q * 4);
    float ds = dinv[n];
    for (int e = beg; e < end; e++) {
        int dst = sdst[e];
        float w = ds * dinv[dst];
        red_add_v4(a + dst * 16 + q * 4, v.x * w, v.y * w, v.z * w, v.w * w);
    }
}

// ---------------- final: out = agg + h*invdeg + bias (mu then ls) -----------
__global__ void out_kernel(const float* __restrict__ aggm, const float* __restrict__ aggl,
                           const float* __restrict__ hm, const float* __restrict__ hl,
                           const float* __restrict__ invdeg, const float* __restrict__ mub,
                           const float* __restrict__ lsb, float* __restrict__ out) {
    int i4 = blockIdx.x * 256 + threadIdx.x;
    int n = i4 >> 2, q = i4 & 3;
    float iv = invdeg[n];
    float4* out4 = reinterpret_cast<float4*>(out);
    float4 am = reinterpret_cast<const float4*>(aggm)[i4];
    float4 vm = reinterpret_cast<const float4*>(hm)[i4];
    float4 bm = reinterpret_cast<const float4*>(mub)[q];
    out4[i4] = make_float4(am.x + vm.x * iv + bm.x, am.y + vm.y * iv + bm.y,
                           am.z + vm.z * iv + bm.z, am.w + vm.w * iv + bm.w);
    float4 al = reinterpret_cast<const float4*>(aggl)[i4];
    float4 vl = reinterpret_cast<const float4*>(hl)[i4];
    float4 bl = reinterpret_cast<const float4*>(lsb)[q];
    out4[32768 + i4] = make_float4(al.x + vl.x * iv + bl.x, al.y + vl.y * iv + bl.y,
                                   al.z + vl.z * iv + bl.z, al.w + vl.w * iv + bl.w);
}

// ---------------- launcher --------------------------------------------------
extern "C" void kernel_launch(void* const* d_in, const int* in_sizes, int n_in,
                              void* d_out, int out_size) {
    const float* x      = (const float*)d_in[0];
    const int*   ei     = (const int*)  d_in[1];
    const float* ea     = (const float*)d_in[2];
    const float* nn1_w  = (const float*)d_in[3];
    const float* nn1_b  = (const float*)d_in[4];
    const float* root1  = (const float*)d_in[5];
    const float* bias1  = (const float*)d_in[6];
    const float* nn2_w  = (const float*)d_in[7];
    const float* nn2_b  = (const float*)d_in[8];
    const float* root2  = (const float*)d_in[9];
    const float* bias2  = (const float*)d_in[10];
    const float* mu_w   = (const float*)d_in[11];
    const float* mu_b   = (const float*)d_in[12];
    const float* ls_w   = (const float*)d_in[13];
    const float* ls_b   = (const float*)d_in[14];
    float* out = (float*)d_out;

    void *pz, *pT1, *pTb1, *pT2, *pTb2, *ph1, *phm, *phl;
    void *pWhl1, *pWhl2, *pdinv, *pinvdeg, *poff, *pcur, *psdst, *psea;
    cudaGetSymbolAddress(&pz, g_zbuf);
    cudaGetSymbolAddress(&pT1, g_T1);
    cudaGetSymbolAddress(&pTb1, g_Tb1);
    cudaGetSymbolAddress(&pT2, g_T2);
    cudaGetSymbolAddress(&pTb2, g_Tb2);
    cudaGetSymbolAddress(&ph1, g_h1);
    cudaGetSymbolAddress(&phm, g_hm);
    cudaGetSymbolAddress(&phl, g_hl);
    cudaGetSymbolAddress(&pWhl1, g_Whl1);
    cudaGetSymbolAddress(&pWhl2, g_Whl2);
    cudaGetSymbolAddress(&pdinv, g_dinv);
    cudaGetSymbolAddress(&pinvdeg, g_invdeg);
    cudaGetSymbolAddress(&poff, g_off);
    cudaGetSymbolAddress(&pcur, g_cursor);
    cudaGetSymbolAddress(&psdst, g_sdst);
    cudaGetSymbolAddress(&psea, g_sea);

    float* zb = (float*)pz;
    int*   deg    = (int*)(zb + OFF_DEG);
    int*   outcnt = (int*)(zb + OFF_OUTCNT);
    float* agg1   = zb + OFF_AGG1;
    float* agg2   = zb + OFF_AGG2;
    float* aggm   = zb + OFF_AGGM;
    float* aggl   = zb + OFF_AGGL;

    // dynamic smem: layer1 = 128*68*4 + 64*68*8 = 34816+34816 = 69632
    //               layer2 = 128*52*4 + 48*68*8 = 26624+26112 = 52736
    cudaFuncSetAttribute(node_gemm_kernel<64, 48>,
                         cudaFuncAttributeMaxDynamicSharedMemorySize, 69632);
    cudaFuncSetAttribute(node_gemm_kernel<48, 32>,
                         cudaFuncAttributeMaxDynamicSharedMemorySize, 52736);

    cudaMemsetAsync(pz, 0, ZFLOATS * sizeof(float), 0);

    prep_kernel<<<418, 256>>>(ei, nn1_w, nn1_b, nn2_w, nn2_b,
                              outcnt, deg, (uint2*)pWhl1, (uint2*)pWhl2);
    scan_dinv_kernel<<<9, 1024>>>(outcnt, deg, (int*)poff, (int*)pcur,
                                  (float*)pdinv, (float*)pinvdeg);
    perm_kernel<<<256, 256>>>(ei, ea, (int*)pcur, (int*)psdst, (float*)psea);

    // layer 1: grid (ceil(432/64)=7, 8192/128=64)
    node_gemm_kernel<64, 48><<<dim3(7, 64), 256, 69632>>>(
        x, (uint2*)pWhl1, (float*)pT1, (float*)pTb1);
    edge_nnconv_kernel<48, 12><<<NN / 32, 384>>>((int*)poff, (int*)psdst, (float*)psea,
                                                 (float*)pT1, (float*)pTb1, agg1);
    root_relu_kernel<64, 48><<<NN / 16, 256>>>(agg1, x, root1, bias1, (float*)ph1);

    // layer 2: grid (ceil(288/64)=5, 64)
    node_gemm_kernel<48, 32><<<dim3(5, 64), 256, 52736>>>(
        (float*)ph1, (uint2*)pWhl2, (float*)pT2, (float*)pTb2);
    edge_nnconv_kernel<32, 8><<<NN / 32, 256>>>((int*)poff, (int*)psdst, (float*)psea,
                                                (float*)pT2, (float*)pTb2, agg2);
    root2_heads_kernel<<<NN / 16, 256>>>(agg2, (float*)ph1, root2, bias2,
                                         mu_w, ls_w, (float*)phm, (float*)phl);

    // GCN scatter + output
    gcn_edge_kernel<<<NN / 32, 256>>>((int*)poff, (int*)psdst, (float*)phm, (float*)phl,
                                      (float*)pdinv, aggm, aggl);
    out_kernel<<<128, 256>>>(aggm, aggl, (float*)phm, (float*)phl,
                             (float*)pinvdeg, mu_b, ls_b, out);
}

// round 11
// speedup vs baseline: 1.7316x; 1.0944x over previous
#include <cuda_runtime.h>
#include <cstdint>

#define NN 8192
#define NE 65536

typedef unsigned long long ull;

// ---------------- zeroed scratch blob (single memset) -----------------------
#define OFF_DEG    0
#define OFF_OUTCNT 8192
#define OFF_AGG1   16384
#define OFF_AGG2   409600
#define OFF_AGGM   671744
#define OFF_AGGL   802816
#define ZFLOATS    933888
__device__ __align__(16) float g_zbuf[ZFLOATS];

// ---------------- other scratch ---------------------------------------------
__device__ __align__(16) float g_T1[NN * 48 * 8];
__device__ __align__(16) float g_Tb1[NN * 48];
__device__ __align__(16) float g_T2[NN * 32 * 8];
__device__ __align__(16) float g_Tb2[NN * 32];
__device__ __align__(16) float g_h1[NN * 48];
__device__ __align__(16) float g_hm[NN * 16];
__device__ __align__(16) float g_hl[NN * 16];
__device__ __align__(16) float g_sea[NE * 8];   // edge_attr in src-sorted order
__device__ int   g_sdst[NE];                    // dst in src-sorted order
__device__ int   g_off[NN + 1];                 // CSR offsets by src
__device__ int   g_cursor[NN];
// bf16 hi/lo pre-packed B fragments: [kchunk][colpad][tig] uint4 {bh0,bh1,bl0,bl1}
__device__ __align__(16) uint4 g_Wb1[4 * 448 * 4];   // K=64: 4 kchunks, NCPAD=448
__device__ __align__(16) uint4 g_Wb2[3 * 320 * 4];   // K=48: 3 kchunks, NCPAD=320
__device__ float g_dinv[NN];
__device__ float g_invdeg[NN];

__device__ __forceinline__ void red_add_v4(float* p, float a, float b, float c, float d) {
    asm volatile("red.global.add.v4.f32 [%0], {%1,%2,%3,%4};"
                 :: "l"(p), "f"(a), "f"(b), "f"(c), "f"(d) : "memory");
}

// pack two floats to bf16x2: low half = lo_elem (lower k index)
__device__ __forceinline__ uint32_t pack_bf16x2(float lo_elem, float hi_elem) {
    uint32_t r;
    asm("cvt.rn.bf16x2.f32 %0, %1, %2;" : "=r"(r) : "f"(hi_elem), "f"(lo_elem));
    return r;
}

__device__ __forceinline__ void mma_bf16(float* c, const uint32_t* a, const uint32_t* b) {
    asm("mma.sync.aligned.m16n8k16.row.col.f32.bf16.bf16.f32 "
        "{%0,%1,%2,%3}, {%4,%5,%6,%7}, {%8,%9}, {%0,%1,%2,%3};"
        : "+f"(c[0]), "+f"(c[1]), "+f"(c[2]), "+f"(c[3])
        : "r"(a[0]), "r"(a[1]), "r"(a[2]), "r"(a[3]), "r"(b[0]), "r"(b[1]));
}

// split a pair (v0,v1) -> {hi packed, lo packed}
__device__ __forceinline__ uint2 split_pair(float v0, float v1) {
    uint32_t h = pack_bf16x2(v0, v1);
    float h0 = __uint_as_float(h << 16);
    float h1 = __uint_as_float(h & 0xFFFF0000u);
    uint32_t l = pack_bf16x2(v0 - h0, v1 - h1);
    return make_uint2(h, l);
}

// ---------------- prep: degree/outdeg counts + pre-packed bf16 weights ------
// logical W1[k][c]: c<384: o=c>>3,s=c&7 -> nn1w[s*3072+k*48+o]; c<432: nn1b[k*48+c-384]; else 0
__device__ __forceinline__ float getw1(const float* w, const float* b, int k, int c) {
    if (c < 384) { int o = c >> 3, s = c & 7; return w[s * 3072 + k * 48 + o]; }
    if (c < 432) return b[k * 48 + (c - 384)];
    return 0.f;
}
__device__ __forceinline__ float getw2(const float* w, const float* b, int k, int c) {
    if (c < 256) { int o = c >> 3, s = c & 7; return w[s * 1536 + k * 32 + o]; }
    if (c < 288) return b[k * 32 + (c - 256)];
    return 0.f;
}

__global__ void prep_kernel(const int* __restrict__ ei,
                            const float* __restrict__ nn1w, const float* __restrict__ nn1b,
                            const float* __restrict__ nn2w, const float* __restrict__ nn2b,
                            int* __restrict__ outcnt, int* __restrict__ deg,
                            uint4* __restrict__ Wb1, uint4* __restrict__ Wb2) {
    int bx = blockIdx.x, t = threadIdx.x;
    if (bx < 256) {
        int e = bx * 256 + t;
        atomicAdd(&outcnt[ei[e]], 1);
        atomicAdd(&deg[ei[NE + e]], 1);
    } else if (bx < 284) {               // 7168 entries: layer1, NCPAD=448, 4 kchunks
        int idx = (bx - 256) * 256 + t;
        int kc = idx / 1792, rem = idx - kc * 1792;
        int col = rem >> 2, tig = rem & 3;
        int k0 = kc * 16 + tig * 2;
        uint2 p0 = split_pair(getw1(nn1w, nn1b, k0,     col), getw1(nn1w, nn1b, k0 + 1, col));
        uint2 p1 = split_pair(getw1(nn1w, nn1b, k0 + 8, col), getw1(nn1w, nn1b, k0 + 9, col));
        Wb1[idx] = make_uint4(p0.x, p1.x, p0.y, p1.y);
    } else {                              // 3840 entries: layer2, NCPAD=320, 3 kchunks
        int idx = (bx - 284) * 256 + t;
        if (idx < 3840) {
            int kc = idx / 1280, rem = idx - kc * 1280;
            int col = rem >> 2, tig = rem & 3;
            int k0 = kc * 16 + tig * 2;
            uint2 p0 = split_pair(getw2(nn2w, nn2b, k0,     col), getw2(nn2w, nn2b, k0 + 1, col));
            uint2 p1 = split_pair(getw2(nn2w, nn2b, k0 + 8, col), getw2(nn2w, nn2b, k0 + 9, col));
            Wb2[idx] = make_uint4(p0.x, p1.x, p0.y, p1.y);
        }
    }
}

// ---------------- block 0: exclusive scan of outcnt; blocks 1..8: dinv ------
__global__ void scan_dinv_kernel(const int* __restrict__ outcnt, const int* __restrict__ deg,
                                 int* __restrict__ off, int* __restrict__ cursor,
                                 float* __restrict__ dinv, float* __restrict__ invdeg) {
    int t = threadIdx.x;
    if (blockIdx.x == 0) {
        __shared__ int wsum[32];
        int base = t * 8;
        int v[8];
        int s = 0;
#pragma unroll
        for (int j = 0; j < 8; j++) { v[j] = outcnt[base + j]; s += v[j]; }
        int lane = t & 31, wid = t >> 5;
        int inc = s;
#pragma unroll
        for (int d = 1; d < 32; d <<= 1) {
            int n = __shfl_up_sync(0xFFFFFFFFu, inc, d);
            if (lane >= d) inc += n;
        }
        int excl_warp = inc - s;
        if (lane == 31) wsum[wid] = inc;
        __syncthreads();
        if (t < 32) {
            int w = wsum[t];
            int wi = w;
#pragma unroll
            for (int d = 1; d < 32; d <<= 1) {
                int n = __shfl_up_sync(0xFFFFFFFFu, wi, d);
                if (t >= d) wi += n;
            }
            wsum[t] = wi - w;
        }
        __syncthreads();
        int run = wsum[wid] + excl_warp;
#pragma unroll
        for (int j = 0; j < 8; j++) {
            off[base + j] = run;
            cursor[base + j] = run;
            run += v[j];
        }
        if (t == 1023) off[NN] = NE;
    } else {
        int n = (blockIdx.x - 1) * 1024 + t;
        float d = (float)deg[n] + 1.0f;
        dinv[n] = rsqrtf(d);
        invdeg[n] = 1.0f / d;
    }
}

// ---------------- scatter edge payloads into src-sorted order ---------------
__global__ void perm_kernel(const int* __restrict__ ei, const float* __restrict__ ea,
                            int* __restrict__ cursor,
                            int* __restrict__ sdst, float* __restrict__ sea) {
    int e = blockIdx.x * 256 + threadIdx.x;
    int s = ei[e];
    int pos = atomicAdd(&cursor[s], 1);
    sdst[pos] = ei[NE + e];
    const float4* ev = reinterpret_cast<const float4*>(ea + e * 8);
    float4* sv = reinterpret_cast<float4*>(sea + pos * 8);
    sv[0] = ev[0];
    sv[1] = ev[1];
}

// ---------------- node GEMM: bf16 3-term split, m16n8k16 mma ----------------
// Block: 256 thr (8 warps). Tile: 128 rows x 64 cols. Warp: 16 rows.
// Per kchunk(16) per n-tile: 1x LDS.128 (B frags, linear/conflict-free) + 3 MMA.
template<int K, int CO, int NCPAD>
__global__ void __launch_bounds__(256) node_gemm_kernel(
        const float* __restrict__ X, const uint4* __restrict__ Wb,
        float* __restrict__ T, float* __restrict__ Tb) {
    constexpr int NC = CO * 9;
    constexpr int XP = K + 2;      // Xs row stride (floats), even
    constexpr int XPH = XP / 2;
    constexpr int KS = K / 16;
    extern __shared__ char smem_raw[];
    float* Xs = reinterpret_cast<float*>(smem_raw);                  // [128][XP]
    uint4* Ws = reinterpret_cast<uint4*>(smem_raw + 128 * XP * 4);   // [KS][64][4]
    int tid = threadIdx.x;
    int n0 = blockIdx.y * 128;
    int cbase = blockIdx.x * 64;

    // fill Xs (row-padded) with float2
    {
        const float2* X2 = reinterpret_cast<const float2*>(X + n0 * K);
        float2* Xs2 = reinterpret_cast<float2*>(Xs);
        for (int idx = tid; idx < 128 * (K / 2); idx += 256) {
            int r = idx / (K / 2), q = idx - r * (K / 2);
            Xs2[r * XPH + q] = X2[r * (K / 2) + q];
        }
    }
    // fill Ws: one uint4 per (kchunk, col, tig)
    for (int idx = tid; idx < KS * 256; idx += 256) {
        int kc = idx >> 8, rem = idx & 255;    // rem = col*4 + tig
        Ws[idx] = Wb[kc * (NCPAD * 4) + cbase * 4 + rem];
    }
    __syncthreads();

    int lane = tid & 31, wp = tid >> 5;
    int gid = lane >> 2;
    int tig = lane & 3;
    int arow = wp * 16 + gid;

    float acc[8][4];
#pragma unroll
    for (int nt = 0; nt < 8; nt++)
#pragma unroll
        for (int j = 0; j < 4; j++) acc[nt][j] = 0.f;

    const float2* xr0 = reinterpret_cast<const float2*>(Xs) + arow * XPH + tig;
    const float2* xr1 = xr0 + 8 * XPH;

#pragma unroll
    for (int kc = 0; kc < KS; kc++) {
        float2 p0 = xr0[kc * 8];        // (arow,   k0..k0+1)
        float2 p1 = xr1[kc * 8];        // (arow+8, k0..k0+1)
        float2 p2 = xr0[kc * 8 + 4];    // (arow,   k0+8..+9)
        float2 p3 = xr1[kc * 8 + 4];    // (arow+8, k0+8..+9)
        uint32_t ah[4], al[4];
        {
            uint2 s0 = split_pair(p0.x, p0.y); ah[0] = s0.x; al[0] = s0.y;
            uint2 s1 = split_pair(p1.x, p1.y); ah[1] = s1.x; al[1] = s1.y;
            uint2 s2 = split_pair(p2.x, p2.y); ah[2] = s2.x; al[2] = s2.y;
            uint2 s3 = split_pair(p3.x, p3.y); ah[3] = s3.x; al[3] = s3.y;
        }
#pragma unroll
        for (int nt = 0; nt < 8; nt++) {
            uint4 b = Ws[(kc * 64 + nt * 8 + gid) * 4 + tig];
            uint32_t bh[2] = { b.x, b.y };
            uint32_t bl[2] = { b.z, b.w };
            mma_bf16(acc[nt], al, bh);
            mma_bf16(acc[nt], ah, bl);
            mma_bf16(acc[nt], ah, bh);
        }
    }

    int r0 = n0 + arow;
#pragma unroll
    for (int nt = 0; nt < 8; nt++) {
        int c = cbase + nt * 8 + tig * 2;
        if (c < NC) {
            if (c < CO * 8) {
                T[r0 * (CO * 8) + c]           = acc[nt][0];
                T[r0 * (CO * 8) + c + 1]       = acc[nt][1];
                T[(r0 + 8) * (CO * 8) + c]     = acc[nt][2];
                T[(r0 + 8) * (CO * 8) + c + 1] = acc[nt][3];
            } else {
                int cc = c - CO * 8;
                Tb[r0 * CO + cc]           = acc[nt][0];
                Tb[r0 * CO + cc + 1]       = acc[nt][1];
                Tb[(r0 + 8) * CO + cc]     = acc[nt][2];
                Tb[(r0 + 8) * CO + cc + 1] = acc[nt][3];
            }
        }
    }
}

// ---------------- edge NNConv: node-parallel over src-CSR -------------------
template<int CO, int TPN>
__global__ void __launch_bounds__(32 * TPN) edge_nnconv_kernel(
        const int* __restrict__ off, const int* __restrict__ sdst,
        const float* __restrict__ sea,
        const float* __restrict__ T, const float* __restrict__ Tb,
        float* __restrict__ agg) {
    int t = threadIdx.x;
    int g = t / TPN;
    int o0 = (t - g * TPN) * 4;
    int n = blockIdx.x * 32 + g;

    int beg = off[n], end = off[n + 1];
    if (beg == end) return;

    const float4* tp = reinterpret_cast<const float4*>(T + (n * CO + o0) * 8);
    float4 T0 = tp[0], T1 = tp[1], T2 = tp[2], T3 = tp[3];
    float4 T4 = tp[4], T5 = tp[5], T6 = tp[6], T7 = tp[7];
    float4 bb = *reinterpret_cast<const float4*>(Tb + n * CO + o0);

    for (int e = beg; e < end; e++) {
        int dst = sdst[e];
        const float4* eap = reinterpret_cast<const float4*>(sea + e * 8);
        float4 a0 = eap[0], a1 = eap[1];
        float r0 = bb.x + a0.x * T0.x + a0.y * T0.y + a0.z * T0.z + a0.w * T0.w
                        + a1.x * T1.x + a1.y * T1.y + a1.z * T1.z + a1.w * T1.w;
        float r1 = bb.y + a0.x * T2.x + a0.y * T2.y + a0.z * T2.z + a0.w * T2.w
                        + a1.x * T3.x + a1.y * T3.y + a1.z * T3.z + a1.w * T3.w;
        float r2 = bb.z + a0.x * T4.x + a0.y * T4.y + a0.z * T4.z + a0.w * T4.w
                        + a1.x * T5.x + a1.y * T5.y + a1.z * T5.z + a1.w * T5.w;
        float r3 = bb.w + a0.x * T6.x + a0.y * T6.y + a0.z * T6.z + a0.w * T6.w
                        + a1.x * T7.x + a1.y * T7.y + a1.z * T7.z + a1.w * T7.w;
        red_add_v4(agg + dst * CO + o0, r0, r1, r2, r3);
    }
}

// ---------------- H = relu(agg + X @ root + bias) ---------------------------
template<int K, int CO>
__global__ void root_relu_kernel(const float* __restrict__ agg, const float* __restrict__ X,
                                 const float* __restrict__ root, const float* __restrict__ bias,
                                 float* __restrict__ H) {
    constexpr int NB = 16;
    constexpr int ITEMS = NB * CO / 256;
    __shared__ float xs[NB][K];
    int n0 = blockIdx.x * NB;
    for (int idx = threadIdx.x; idx < NB * K; idx += 256)
        xs[idx / K][idx % K] = X[n0 * K + idx];
    __syncthreads();
#pragma unroll
    for (int j = 0; j < ITEMS; j++) {
        int item = threadIdx.x + j * 256;
        int nl = item / CO, o = item - nl * CO;
        float acc = agg[(n0 + nl) * CO + o] + bias[o];
#pragma unroll 4
        for (int i = 0; i < K; i++) acc += xs[nl][i] * root[i * CO + o];
        H[(n0 + nl) * CO + o] = fmaxf(acc, 0.f);
    }
}

// ---------------- fused: h2 = relu(...); hm = h2@muw; hl = h2@lsw -----------
__global__ void root2_heads_kernel(const float* __restrict__ agg, const float* __restrict__ H1,
                                   const float* __restrict__ root, const float* __restrict__ bias,
                                   const float* __restrict__ muw, const float* __restrict__ lsw,
                                   float* __restrict__ hm, float* __restrict__ hl) {
    __shared__ float xs[16][48];
    __shared__ float hs[16][32];
    int n0 = blockIdx.x * 16;
    for (int idx = threadIdx.x; idx < 16 * 48; idx += 256)
        xs[idx / 48][idx % 48] = H1[n0 * 48 + idx];
    __syncthreads();
#pragma unroll
    for (int j = 0; j < 2; j++) {
        int item = threadIdx.x + j * 256;
        int nl = item >> 5, o = item & 31;
        float acc = agg[(n0 + nl) * 32 + o] + bias[o];
#pragma unroll 4
        for (int i = 0; i < 48; i++) acc += xs[nl][i] * root[i * 32 + o];
        hs[nl][o] = fmaxf(acc, 0.f);
    }
    __syncthreads();
#pragma unroll
    for (int j = 0; j < 2; j++) {
        int item = threadIdx.x + j * 256;
        int nl = item >> 5;
        int r = item & 31;
        int head = r >> 4, o = r & 15;
        const float* W = head ? lsw : muw;
        float acc = 0.f;
#pragma unroll
        for (int i = 0; i < 32; i++) acc += hs[nl][i] * W[i * 16 + o];
        (head ? hl : hm)[(n0 + nl) * 16 + o] = acc;
    }
}

// ---------------- GCN scatter: node-parallel over src-CSR -------------------
__global__ void __launch_bounds__(256) gcn_edge_kernel(
        const int* __restrict__ off, const int* __restrict__ sdst,
        const float* __restrict__ hm, const float* __restrict__ hl,
        const float* __restrict__ dinv,
        float* __restrict__ aggm, float* __restrict__ aggl) {
    int t = threadIdx.x;
    int g = t >> 3;
    int r = t & 7;
    int head = r >> 2, q = r & 3;
    int n = blockIdx.x * 32 + g;
    int beg = off[n], end = off[n + 1];
    if (beg == end) return;

    const float* h = head ? hl : hm;
    float* a = head ? aggl : aggm;
    float4 v = *reinterpret_cast<const float4*>(h + n * 16 + q * 4);
    float ds = dinv[n];
    for (int e = beg; e < end; e++) {
        int dst = sdst[e];
        float w = ds * dinv[dst];
        red_add_v4(a + dst * 16 + q * 4, v.x * w, v.y * w, v.z * w, v.w * w);
    }
}

// ---------------- final: out = agg + h*invdeg + bias (mu then ls) -----------
__global__ void out_kernel(const float* __restrict__ aggm, const float* __restrict__ aggl,
                           const float* __restrict__ hm, const float* __restrict__ hl,
                           const float* __restrict__ invdeg, const float* __restrict__ mub,
                           const float* __restrict__ lsb, float* __restrict__ out) {
    int i4 = blockIdx.x * 256 + threadIdx.x;
    int n = i4 >> 2, q = i4 & 3;
    float iv = invdeg[n];
    float4* out4 = reinterpret_cast<float4*>(out);
    float4 am = reinterpret_cast<const float4*>(aggm)[i4];
    float4 vm = reinterpret_cast<const float4*>(hm)[i4];
    float4 bm = reinterpret_cast<const float4*>(mub)[q];
    out4[i4] = make_float4(am.x + vm.x * iv + bm.x, am.y + vm.y * iv + bm.y,
                           am.z + vm.z * iv + bm.z, am.w + vm.w * iv + bm.w);
    float4 al = reinterpret_cast<const float4*>(aggl)[i4];
    float4 vl = reinterpret_cast<const float4*>(hl)[i4];
    float4 bl = reinterpret_cast<const float4*>(lsb)[q];
    out4[32768 + i4] = make_float4(al.x + vl.x * iv + bl.x, al.y + vl.y * iv + bl.y,
                                   al.z + vl.z * iv + bl.z, al.w + vl.w * iv + bl.w);
}

// ---------------- launcher --------------------------------------------------
extern "C" void kernel_launch(void* const* d_in, const int* in_sizes, int n_in,
                              void* d_out, int out_size) {
    const float* x      = (const float*)d_in[0];
    const int*   ei     = (const int*)  d_in[1];
    const float* ea     = (const float*)d_in[2];
    const float* nn1_w  = (const float*)d_in[3];
    const float* nn1_b  = (const float*)d_in[4];
    const float* root1  = (const float*)d_in[5];
    const float* bias1  = (const float*)d_in[6];
    const float* nn2_w  = (const float*)d_in[7];
    const float* nn2_b  = (const float*)d_in[8];
    const float* root2  = (const float*)d_in[9];
    const float* bias2  = (const float*)d_in[10];
    const float* mu_w   = (const float*)d_in[11];
    const float* mu_b   = (const float*)d_in[12];
    const float* ls_w   = (const float*)d_in[13];
    const float* ls_b   = (const float*)d_in[14];
    float* out = (float*)d_out;

    void *pz, *pT1, *pTb1, *pT2, *pTb2, *ph1, *phm, *phl;
    void *pWb1, *pWb2, *pdinv, *pinvdeg, *poff, *pcur, *psdst, *psea;
    cudaGetSymbolAddress(&pz, g_zbuf);
    cudaGetSymbolAddress(&pT1, g_T1);
    cudaGetSymbolAddress(&pTb1, g_Tb1);
    cudaGetSymbolAddress(&pT2, g_T2);
    cudaGetSymbolAddress(&pTb2, g_Tb2);
    cudaGetSymbolAddress(&ph1, g_h1);
    cudaGetSymbolAddress(&phm, g_hm);
    cudaGetSymbolAddress(&phl, g_hl);
    cudaGetSymbolAddress(&pWb1, g_Wb1);
    cudaGetSymbolAddress(&pWb2, g_Wb2);
    cudaGetSymbolAddress(&pdinv, g_dinv);
    cudaGetSymbolAddress(&pinvdeg, g_invdeg);
    cudaGetSymbolAddress(&poff, g_off);
    cudaGetSymbolAddress(&pcur, g_cursor);
    cudaGetSymbolAddress(&psdst, g_sdst);
    cudaGetSymbolAddress(&psea, g_sea);

    float* zb = (float*)pz;
    int*   deg    = (int*)(zb + OFF_DEG);
    int*   outcnt = (int*)(zb + OFF_OUTCNT);
    float* agg1   = zb + OFF_AGG1;
    float* agg2   = zb + OFF_AGG2;
    float* aggm   = zb + OFF_AGGM;
    float* aggl   = zb + OFF_AGGL;

    // dynamic smem: layer1 = 128*66*4 + 4*256*16 = 33792 + 16384 = 50176
    //               layer2 = 128*50*4 + 3*256*16 = 25600 + 12288 = 37888
    cudaFuncSetAttribute(node_gemm_kernel<64, 48, 448>,
                         cudaFuncAttributeMaxDynamicSharedMemorySize, 50176);
    cudaFuncSetAttribute(node_gemm_kernel<48, 32, 320>,
                         cudaFuncAttributeMaxDynamicSharedMemorySize, 37888);

    cudaMemsetAsync(pz, 0, ZFLOATS * sizeof(float), 0);

    prep_kernel<<<299, 256>>>(ei, nn1_w, nn1_b, nn2_w, nn2_b,
                              outcnt, deg, (uint4*)pWb1, (uint4*)pWb2);
    scan_dinv_kernel<<<9, 1024>>>(outcnt, deg, (int*)poff, (int*)pcur,
                                  (float*)pdinv, (float*)pinvdeg);
    perm_kernel<<<256, 256>>>(ei, ea, (int*)pcur, (int*)psdst, (float*)psea);

    // layer 1: grid (448/64=7, 8192/128=64)
    node_gemm_kernel<64, 48, 448><<<dim3(7, 64), 256, 50176>>>(
        x, (uint4*)pWb1, (float*)pT1, (float*)pTb1);
    edge_nnconv_kernel<48, 12><<<NN / 32, 384>>>((int*)poff, (int*)psdst, (float*)psea,
                                                 (float*)pT1, (float*)pTb1, agg1);
    root_relu_kernel<64, 48><<<NN / 16, 256>>>(agg1, x, root1, bias1, (float*)ph1);

    // layer 2: grid (320/64=5, 64)
    node_gemm_kernel<48, 32, 320><<<dim3(5, 64), 256, 37888>>>(
        (float*)ph1, (uint4*)pWb2, (float*)pT2, (float*)pTb2);
    edge_nnconv_kernel<32, 8><<<NN / 32, 256>>>((int*)poff, (int*)psdst, (float*)psea,
                                                (float*)pT2, (float*)pTb2, agg2);
    root2_heads_kernel<<<NN / 16, 256>>>(agg2, (float*)ph1, root2, bias2,
                                         mu_w, ls_w, (float*)phm, (float*)phl);

    // GCN scatter + output
    gcn_edge_kernel<<<NN / 32, 256>>>((int*)poff, (int*)psdst, (float*)phm, (float*)phl,
                                      (float*)pdinv, aggm, aggl);
    out_kernel<<<128, 256>>>(aggm, aggl, (float*)phm, (float*)phl,
                             (float*)pinvdeg, mu_b, ls_b, out);
}